// round 15
// baseline (speedup 1.0000x reference)
#include <cuda_runtime.h>
#include <cuda_fp16.h>
#include <cstdint>

typedef uint32_t u32;
typedef unsigned long long ull;

#define CHUNKSZ 512
#define NCHUNK  8
#define HH      1024
#define FF      4096
#define MROWS   2048          /* rows per chunk (B*CHUNKSZ) */
#define MALL    16384         /* all rows (B*S) */
#define NOUT    16777216
#define NTEN    3584          /* gemm1 cols on tensor path; [NTEN,FF) on SIMT path */

// ---- scratch (device globals; no allocations allowed) ----
__device__ __half g_xh [(size_t)NOUT];         // fp16 x (32MB)
__device__ __half g_u0h[(size_t)MALL * FF];    // u0 all chunks (128MB)
__device__ __half g_u2h[(size_t)MALL * FF];    // u2 all chunks (128MB)
__device__ __half g_vh [(size_t)MROWS * FF];   // v, chunk-local (16MB)
__device__ __half g_w0T[(size_t)FF * HH];      // w0^T [n=4096][k=1024]
__device__ __half g_w2T[(size_t)FF * HH];
__device__ __half g_w1T[(size_t)HH * FF];      // w1^T [n=1024][k=4096]
__device__ float g_partial[256];
__device__ float g_D;
__device__ float g_total;

// =================== helpers ===================
__device__ __forceinline__ u32 smem_u32(const void* p) {
    u32 a; asm("{ .reg .u64 t; cvta.to.shared.u64 t, %1; cvt.u32.u64 %0, t; }" : "=r"(a) : "l"(p));
    return a;
}

#define CP16(dst, src) \
    asm volatile("cp.async.cg.shared.global [%0], [%1], 16;" :: "r"(dst), "l"(src) : "memory")
#define CPCOMMIT() asm volatile("cp.async.commit_group;" ::: "memory")
#define CPWAIT1()  asm volatile("cp.async.wait_group 1;" ::: "memory")
#define CPWAIT2()  asm volatile("cp.async.wait_group 2;" ::: "memory")

#define LDSM4(r, addr) \
    asm volatile("ldmatrix.sync.aligned.m8n8.x4.shared.b16 {%0,%1,%2,%3}, [%4];" \
        : "=r"((r)[0]), "=r"((r)[1]), "=r"((r)[2]), "=r"((r)[3]) : "r"(addr))

#define MMA16(d, a, b0_, b1_) \
    asm volatile("mma.sync.aligned.m16n8k16.row.col.f32.f16.f16.f32 " \
        "{%0,%1,%2,%3}, {%4,%5,%6,%7}, {%8,%9}, {%0,%1,%2,%3};" \
        : "+f"((d)[0]), "+f"((d)[1]), "+f"((d)[2]), "+f"((d)[3]) \
        : "r"((a)[0]), "r"((a)[1]), "r"((a)[2]), "r"((a)[3]), "r"(b0_), "r"(b1_))

// packed f32x2 helpers (full-rate fp32 SIMT path)
__device__ __forceinline__ ull fma2(ull a, ull b, ull c) {
    ull d; asm("fma.rn.f32x2 %0, %1, %2, %3;" : "=l"(d) : "l"(a), "l"(b), "l"(c)); return d;
}
__device__ __forceinline__ ull dup2(float a) {
    ull d; asm("mov.b64 %0, {%1, %1};" : "=l"(d) : "f"(a)); return d;
}
__device__ __forceinline__ float2 unpk(ull v) {
    float2 r; asm("mov.b64 {%0, %1}, %2;" : "=f"(r.x), "=f"(r.y) : "l"(v)); return r;
}

// rows x 64 k-halves (128B data), row stride 144B -> conflict-free LDSM/STS
#define ROWSTRB  144
#define TILE128  18432   /* 128*144 */
#define TILE64   9216    /*  64*144 */
#define MROWB    2304    /*  16*144 */

// =================== small kernels ===================
__global__ void conv_x_kernel(const float* __restrict__ x) {
    int i = (blockIdx.x * 256 + threadIdx.x) * 4;
    float4 v = *(const float4*)(x + i);
    *(__half2*)(g_xh + i)     = __floats2half2_rn(v.x, v.y);
    *(__half2*)(g_xh + i + 2) = __floats2half2_rn(v.z, v.w);
    if (blockIdx.x == 0 && threadIdx.x == 0) { g_D = 1.0f; g_total = 0.0f; }
}

// 3 transposes in one launch (z selects weight); out[C][R] = half(in[R][C])
__global__ void transpose_all(const float* __restrict__ w0, const float* __restrict__ w1,
                              const float* __restrict__ w2) {
    __shared__ float t[32][33];
    int z = blockIdx.z;
    const float* in; __half* out; int R, C, c0, r0;
    if (z == 0)      { in = w0; out = g_w0T; R = HH; C = FF; c0 = blockIdx.x * 32; r0 = blockIdx.y * 32; }
    else if (z == 1) { in = w2; out = g_w2T; R = HH; C = FF; c0 = blockIdx.x * 32; r0 = blockIdx.y * 32; }
    else             { in = w1; out = g_w1T; R = FF; C = HH; c0 = blockIdx.y * 32; r0 = blockIdx.x * 32; }
    #pragma unroll
    for (int i = 0; i < 32; i += 8)
        t[threadIdx.y + i][threadIdx.x] = in[(size_t)(r0 + threadIdx.y + i) * C + c0 + threadIdx.x];
    __syncthreads();
    #pragma unroll
    for (int i = 0; i < 32; i += 8)
        out[(size_t)(c0 + threadIdx.y + i) * R + r0 + threadIdx.x] = __float2half_rn(t[threadIdx.x][threadIdx.y + i]);
}

// vh[row_local] = silu(D*u0[grow]) * u2[grow], 8 halves/thread
__global__ void silu_mul_kernel(int chunk) {
    const float D = g_D;
    size_t idx = ((size_t)blockIdx.x * 256 + threadIdx.x) * 8;
    int rl  = (int)(idx >> 12);
    int col = (int)(idx & 4095);
    int grow = ((rl >> 9) << 12) + chunk * CHUNKSZ + (rl & 511);
    size_t gi = (size_t)grow * FF + col;
    uint4 a4 = *(const uint4*)(g_u0h + gi);
    uint4 b4 = *(const uint4*)(g_u2h + gi);
    const __half2* a = (const __half2*)&a4;
    const __half2* b = (const __half2*)&b4;
    uint4 o4;
    __half2* o = (__half2*)&o4;
    #pragma unroll
    for (int j = 0; j < 4; j++) {
        float2 af = __half22float2(a[j]);
        float2 bf = __half22float2(b[j]);
        float z0 = D * af.x, z1 = D * af.y;
        float s0 = z0 / (1.0f + __expf(-z0)), s1 = z1 / (1.0f + __expf(-z1));
        o[j] = __floats2half2_rn(s0 * bf.x, s1 * bf.y);
    }
    *(uint4*)(g_vh + (size_t)rl * FF + col) = o4;
}

__global__ void reduce_update_kernel(float* __restrict__ outp, int chunk) {
    __shared__ float red[256];
    int t = threadIdx.x;
    red[t] = g_partial[t];
    __syncthreads();
    for (int s = 128; s > 0; s >>= 1) {
        if (t < s) red[t] += red[t + s];
        __syncthreads();
    }
    if (t == 0) {
        float loss = red[0] * (1.0f / (float)(MROWS * HH));
        float tot = g_total + loss;
        g_total = tot;
        g_D = g_D * (1.0f - 0.001f * loss);
        if (chunk == NCHUNK - 1) outp[NOUT] = tot * (1.0f / (float)NCHUNK);
    }
}

// =================== GEMM1-SIMT (fp32 fma pipe): cols [NTEN, FF) of u{0,2} ===================
// 128x128 tile, 256 thr, 8x8/thread via f32x2 (round-1 proven kernel), per-chunk rows.
__global__ __launch_bounds__(256, 2)
void gemm1_simt(const float* __restrict__ x,
                const float* __restrict__ B0,
                const float* __restrict__ B1,
                int chunk)
{
    __shared__ float As[2][16][128];
    __shared__ float Bs[2][16][128];

    const int tid = threadIdx.x;
    const int m0 = blockIdx.y * 128;              // chunk-local row
    const int n0g = NTEN + blockIdx.x * 128;      // global col
    const float* Bsrc = blockIdx.z ? B1 : B0;     // w0 or w2 [1024 x 4096] row-major
    __half* uout = blockIdx.z ? g_u2h : g_u0h;

    const int r0 = tid >> 2, c4 = tid & 3;
    const int mA0 = m0 + r0, mA1 = m0 + r0 + 64;
    const int ga0 = ((mA0 >> 9) << 12) + chunk * CHUNKSZ + (mA0 & 511);
    const int ga1 = ((mA1 >> 9) << 12) + chunk * CHUNKSZ + (mA1 & 511);
    const float* pa0 = x + (size_t)ga0 * HH + c4 * 4;
    const float* pa1 = x + (size_t)ga1 * HH + c4 * 4;
    const int kr = tid >> 5, nc = tid & 31;
    const float* pb0 = Bsrc + (size_t)kr * FF + n0g + nc * 4;
    const float* pb1 = pb0 + (size_t)8 * FF;

    ull acc[8][4];
    #pragma unroll
    for (int i = 0; i < 8; i++)
        #pragma unroll
        for (int j = 0; j < 4; j++) acc[i][j] = 0ull;

    float4 ra0 = *(const float4*)pa0;
    float4 ra1 = *(const float4*)pa1;
    float4 rb0 = *(const float4*)pb0;
    float4 rb1 = *(const float4*)pb1;
    pa0 += 16; pa1 += 16;
    pb0 += (size_t)16 * FF; pb1 += (size_t)16 * FF;

    As[0][c4*4+0][r0] = ra0.x; As[0][c4*4+1][r0] = ra0.y;
    As[0][c4*4+2][r0] = ra0.z; As[0][c4*4+3][r0] = ra0.w;
    As[0][c4*4+0][r0+64] = ra1.x; As[0][c4*4+1][r0+64] = ra1.y;
    As[0][c4*4+2][r0+64] = ra1.z; As[0][c4*4+3][r0+64] = ra1.w;
    *(float4*)&Bs[0][kr][nc*4]   = rb0;
    *(float4*)&Bs[0][kr+8][nc*4] = rb1;
    __syncthreads();

    const int tx = tid & 15, ty = tid >> 4;
    const int KT = HH / 16;  // 64

    for (int kt = 0; kt < KT; ++kt) {
        const int buf = kt & 1;
        if (kt + 1 < KT) {
            ra0 = *(const float4*)pa0;
            ra1 = *(const float4*)pa1;
            rb0 = *(const float4*)pb0;
            rb1 = *(const float4*)pb1;
            pa0 += 16; pa1 += 16;
            pb0 += (size_t)16 * FF; pb1 += (size_t)16 * FF;
        }
        #pragma unroll
        for (int k = 0; k < 16; ++k) {
            const float* ap = &As[buf][k][ty * 8];
            float4 av0 = *(const float4*)ap;
            float4 av1 = *(const float4*)(ap + 4);
            const ull* bp = (const ull*)&Bs[buf][k][tx * 8];
            ull bv0 = bp[0], bv1 = bp[1], bv2 = bp[2], bv3 = bp[3];
            float a[8] = {av0.x, av0.y, av0.z, av0.w, av1.x, av1.y, av1.z, av1.w};
            #pragma unroll
            for (int i = 0; i < 8; ++i) {
                ull ai = dup2(a[i]);
                acc[i][0] = fma2(ai, bv0, acc[i][0]);
                acc[i][1] = fma2(ai, bv1, acc[i][1]);
                acc[i][2] = fma2(ai, bv2, acc[i][2]);
                acc[i][3] = fma2(ai, bv3, acc[i][3]);
            }
        }
        if (kt + 1 < KT) {
            const int nb = buf ^ 1;
            As[nb][c4*4+0][r0] = ra0.x; As[nb][c4*4+1][r0] = ra0.y;
            As[nb][c4*4+2][r0] = ra0.z; As[nb][c4*4+3][r0] = ra0.w;
            As[nb][c4*4+0][r0+64] = ra1.x; As[nb][c4*4+1][r0+64] = ra1.y;
            As[nb][c4*4+2][r0+64] = ra1.z; As[nb][c4*4+3][r0+64] = ra1.w;
            *(float4*)&Bs[nb][kr][nc*4]   = rb0;
            *(float4*)&Bs[nb][kr+8][nc*4] = rb1;
        }
        __syncthreads();
    }

    #pragma unroll
    for (int i = 0; i < 8; ++i) {
        const int m = m0 + ty * 8 + i;
        const int grow = ((m >> 9) << 12) + chunk * CHUNKSZ + (m & 511);
        __half* cp = uout + (size_t)grow * FF + n0g + tx * 8;
        float2 p0 = unpk(acc[i][0]), p1 = unpk(acc[i][1]);
        float2 p2 = unpk(acc[i][2]), p3 = unpk(acc[i][3]);
        uint4 pk;
        ((__half2*)&pk)[0] = __floats2half2_rn(p0.x, p0.y);
        ((__half2*)&pk)[1] = __floats2half2_rn(p1.x, p1.y);
        ((__half2*)&pk)[2] = __floats2half2_rn(p2.x, p2.y);
        ((__half2*)&pk)[3] = __floats2half2_rn(p3.x, p3.y);
        *(uint4*)cp = pk;
    }
}

// =================== GEMM1-TC (per chunk): cols [0, NTEN) of u{0,2} ===================
// CTA 128x128, 256 thr (8 warps 4m x 2n, warp 32x64), K=1024, k-tile 64, 3 stages, occ 2.
#define ST1_STAGE (2 * TILE128)    /* 36864 */
#define ST1_BYTES (3 * ST1_STAGE)  /* 110592 */

__device__ __forceinline__ void g1_load(u32 base, const __half* wT, int tid,
                                        int m0, int n0, int kt) {
    #pragma unroll
    for (int i = 0; i < 4; i++) {
        int idx = tid + i * 256;
        int row = idx >> 3, kq = idx & 7;
        CP16(base + (u32)(row * ROWSTRB + kq * 16),
             g_xh + (size_t)(m0 + row) * HH + kt * 64 + kq * 8);
    }
    #pragma unroll
    for (int i = 0; i < 4; i++) {
        int idx = tid + i * 256;
        int row = idx >> 3, kq = idx & 7;
        CP16(base + TILE128 + (u32)(row * ROWSTRB + kq * 16),
             wT + (size_t)(n0 + row) * HH + kt * 64 + kq * 8);
    }
}

__global__ __launch_bounds__(256, 2)
void gemm1_tc(int chunk)
{
    extern __shared__ float smem[];
    const u32 sb = smem_u32(smem);
    const int tid = threadIdx.x, lane = tid & 31, wid = tid >> 5;
    const int wm = wid & 3, wn = wid >> 2;            // 4m x 2n warps, tile 32x64
    const int m0 = ((blockIdx.y >> 2) << 12) + chunk * CHUNKSZ + (blockIdx.y & 3) * 128;
    const int n0 = blockIdx.x * 128;
    const int z = blockIdx.z;
    const __half* wT = z ? g_w2T : g_w0T;
    __half* uout = z ? g_u2h : g_u0h;

    float acc[2][8][4];
    #pragma unroll
    for (int a = 0; a < 2; a++)
        #pragma unroll
        for (int b = 0; b < 8; b++)
            #pragma unroll
            for (int c = 0; c < 4; c++) acc[a][b][c] = 0.f;

    const u32 aoff = (u32)((wm * 32 + (lane & 15)) * ROWSTRB) + ((lane >> 4) & 1) * 16;
    const u32 boff = (u32)((wn * 64 + (lane & 15)) * ROWSTRB) + ((lane >> 4) & 1) * 16;

    g1_load(sb, wT, tid, m0, n0, 0); CPCOMMIT();
    g1_load(sb + ST1_STAGE, wT, tid, m0, n0, 1); CPCOMMIT();

    const int KT = HH / 64;  // 16
    for (int kt = 0; kt < KT; ++kt) {
        const u32 base = sb + (u32)(kt % 3) * ST1_STAGE;
        CPWAIT1();
        __syncthreads();
        if (kt + 2 < KT) g1_load(sb + (u32)((kt + 2) % 3) * ST1_STAGE, wT, tid, m0, n0, kt + 2);
        CPCOMMIT();
        #pragma unroll
        for (int ks = 0; ks < 4; ++ks) {
            u32 A[2][4];
            LDSM4(A[0], base + aoff + 0 * MROWB + ks * 32);
            LDSM4(A[1], base + aoff + 1 * MROWB + ks * 32);
            #pragma unroll
            for (int tp = 0; tp < 4; ++tp) {
                u32 b[4];
                LDSM4(b, base + TILE128 + boff + tp * MROWB + ks * 32);
                #pragma unroll
                for (int mt = 0; mt < 2; ++mt) {
                    MMA16(acc[mt][2 * tp],     A[mt], b[0], b[2]);
                    MMA16(acc[mt][2 * tp + 1], A[mt], b[1], b[3]);
                }
            }
        }
    }

    const int gq = lane >> 2, tg = lane & 3;
    #pragma unroll
    for (int mt = 0; mt < 2; ++mt) {
        #pragma unroll
        for (int nt = 0; nt < 8; ++nt) {
            const int col = n0 + wn * 64 + nt * 8 + tg * 2;
            #pragma unroll
            for (int h = 0; h < 2; ++h) {
                const int row = m0 + wm * 32 + mt * 16 + gq + h * 8;
                *(__half2*)&uout[(size_t)row * FF + col] =
                    __floats2half2_rn(acc[mt][nt][h * 2], acc[mt][nt][h * 2 + 1]);
            }
        }
    }
}

// =================== GEMM2: out = D^2 * (v @ w1T) + fused loss partials ===================
// CTA 64x128, 256 thr (8 warps 2m x 4n, warp 32x32), K=4096, k-tile 64, 4 stages, occ 2.
#define ST2_STAGE (TILE64 + TILE128)  /* 27648 */
#define ST2_BYTES (4 * ST2_STAGE)     /* 110592 */

__device__ __forceinline__ void g2_load(u32 base, int tid, int m0, int n0, int kt) {
    #pragma unroll
    for (int i = 0; i < 2; i++) {
        int idx = tid + i * 256;
        int row = idx >> 3, kq = idx & 7;
        CP16(base + (u32)(row * ROWSTRB + kq * 16),
             g_vh + (size_t)(m0 + row) * FF + kt * 64 + kq * 8);
    }
    #pragma unroll
    for (int i = 0; i < 4; i++) {
        int idx = tid + i * 256;
        int row = idx >> 3, kq = idx & 7;
        CP16(base + TILE64 + (u32)(row * ROWSTRB + kq * 16),
             g_w1T + (size_t)(n0 + row) * FF + kt * 64 + kq * 8);
    }
}

__global__ __launch_bounds__(256, 2)
void gemm2_tc(const float* __restrict__ x, float* __restrict__ outp, int chunk)
{
    extern __shared__ float smem[];
    const u32 sb = smem_u32(smem);
    const int tid = threadIdx.x, lane = tid & 31, wid = tid >> 5;
    const int wm = wid & 1, wn = wid >> 1;            // 2m x 4n warps, tile 32x32
    const int m0 = blockIdx.y * 64, n0 = blockIdx.x * 128;

    float acc[2][4][4];
    #pragma unroll
    for (int a = 0; a < 2; a++)
        #pragma unroll
        for (int b = 0; b < 4; b++)
            #pragma unroll
            for (int c = 0; c < 4; c++) acc[a][b][c] = 0.f;

    const u32 aoff = (u32)((wm * 32 + (lane & 15)) * ROWSTRB) + ((lane >> 4) & 1) * 16;
    const u32 boff = (u32)((wn * 32 + (lane & 15)) * ROWSTRB) + ((lane >> 4) & 1) * 16;

    g2_load(sb, tid, m0, n0, 0); CPCOMMIT();
    g2_load(sb + ST2_STAGE, tid, m0, n0, 1); CPCOMMIT();
    g2_load(sb + 2 * ST2_STAGE, tid, m0, n0, 2); CPCOMMIT();

    const int KT = FF / 64;  // 64
    for (int kt = 0; kt < KT; ++kt) {
        const u32 base = sb + (u32)(kt & 3) * ST2_STAGE;
        CPWAIT2();
        __syncthreads();
        if (kt + 3 < KT) g2_load(sb + (u32)((kt + 3) & 3) * ST2_STAGE, tid, m0, n0, kt + 3);
        CPCOMMIT();
        #pragma unroll
        for (int ks = 0; ks < 4; ++ks) {
            u32 A[2][4], b0[4], b1[4];
            LDSM4(A[0], base + aoff + 0 * MROWB + ks * 32);
            LDSM4(A[1], base + aoff + 1 * MROWB + ks * 32);
            LDSM4(b0, base + TILE64 + boff + 0 * MROWB + ks * 32);
            LDSM4(b1, base + TILE64 + boff + 1 * MROWB + ks * 32);
            #pragma unroll
            for (int mt = 0; mt < 2; ++mt) {
                MMA16(acc[mt][0], A[mt], b0[0], b0[2]);
                MMA16(acc[mt][1], A[mt], b0[1], b0[3]);
                MMA16(acc[mt][2], A[mt], b1[0], b1[2]);
                MMA16(acc[mt][3], A[mt], b1[1], b1[3]);
            }
        }
    }

    const float D = g_D, D2 = D * D;
    const int gq = lane >> 2, tg = lane & 3;
    float sq = 0.0f;
    #pragma unroll
    for (int mt = 0; mt < 2; ++mt) {
        #pragma unroll
        for (int nt = 0; nt < 4; ++nt) {
            const int col = n0 + wn * 32 + nt * 8 + tg * 2;
            #pragma unroll
            for (int h = 0; h < 2; ++h) {
                const int lm = m0 + wm * 32 + mt * 16 + gq + h * 8;
                const int g = ((lm >> 9) << 12) + chunk * CHUNKSZ + (lm & 511);
                float2 xv = *(const float2*)(x + (size_t)g * HH + col);
                float2 ov;
                ov.x = D2 * acc[mt][nt][h * 2];
                ov.y = D2 * acc[mt][nt][h * 2 + 1];
                *(float2*)(outp + (size_t)g * HH + col) = ov;
                float d0 = ov.x - xv.x, d1 = ov.y - xv.y;
                sq += d0 * d0 + d1 * d1;
            }
        }
    }
    #pragma unroll
    for (int off = 16; off > 0; off >>= 1)
        sq += __shfl_xor_sync(0xFFFFFFFFu, sq, off);
    __syncthreads();
    float* red = smem;
    if (lane == 0) red[wid] = sq;
    __syncthreads();
    if (tid == 0) {
        float s = 0.f;
        #pragma unroll
        for (int i = 0; i < 8; i++) s += red[i];
        g_partial[blockIdx.y * 8 + blockIdx.x] = s;
    }
}

// =================== host ===================
extern "C" void kernel_launch(void* const* d_in, const int* in_sizes, int n_in,
                              void* d_out, int out_size)
{
    const float* x  = (const float*)d_in[0];
    const float* w0 = (const float*)d_in[1];
    const float* w1 = (const float*)d_in[2];
    const float* w2 = (const float*)d_in[3];
    float* out = (float*)d_out;

    static cudaStream_t sS = nullptr, sF = nullptr;
    static cudaEvent_t evF = nullptr, evS = nullptr, e1[NCHUNK], e2[NCHUNK];
    if (!sS) {
        int prLo, prHi;
        cudaDeviceGetStreamPriorityRange(&prLo, &prHi);   // prLo = lowest priority
        cudaStreamCreateWithFlags(&sS, cudaStreamNonBlocking);
        cudaStreamCreateWithPriority(&sF, cudaStreamNonBlocking, prLo);
        cudaEventCreateWithFlags(&evF, cudaEventDisableTiming);
        cudaEventCreateWithFlags(&evS, cudaEventDisableTiming);
        for (int c = 0; c < NCHUNK; ++c) {
            cudaEventCreateWithFlags(&e1[c], cudaEventDisableTiming);
            cudaEventCreateWithFlags(&e2[c], cudaEventDisableTiming);
        }
        cudaFuncSetAttribute(gemm1_tc, cudaFuncAttributeMaxDynamicSharedMemorySize, ST1_BYTES);
        cudaFuncSetAttribute(gemm2_tc, cudaFuncAttributeMaxDynamicSharedMemorySize, ST2_BYTES);
    }

    // fork SIMT stream at the very top (needs only raw fp32 inputs)
    cudaEventRecord(evS, 0);
    cudaStreamWaitEvent(sF, evS, 0);
    for (int c = 0; c < NCHUNK; ++c) {
        gemm1_simt<<<dim3(4, 16, 2), 256, 0, sF>>>(x, w0, w2, c);
        cudaEventRecord(e2[c], sF);
    }

    conv_x_kernel<<<NOUT / 1024, 256>>>(x);
    transpose_all<<<dim3(128, 32, 3), dim3(32, 8)>>>(w0, w1, w2);

    // chunk 0's tensor gemm1 on the main stream (needed first)
    gemm1_tc<<<dim3(NTEN / 128, 16, 2), 256, ST1_BYTES>>>(0);

    // fork: side stream computes tensor gemm1 for chunks 1..7 concurrently with the chain
    cudaEventRecord(evF, 0);
    cudaStreamWaitEvent(sS, evF, 0);
    for (int c = 1; c < NCHUNK; ++c) {
        gemm1_tc<<<dim3(NTEN / 128, 16, 2), 256, ST1_BYTES, sS>>>(c);
        cudaEventRecord(e1[c], sS);
    }

    // serial D-recurrence chain; chain(c) gated on tensor gemm1(c) AND simt gemm1(c)
    for (int c = 0; c < NCHUNK; ++c) {
        if (c > 0) cudaStreamWaitEvent(0, e1[c], 0);
        cudaStreamWaitEvent(0, e2[c], 0);              // joins sF by c=7
        silu_mul_kernel<<<(MROWS * FF) / 2048, 256>>>(c);
        gemm2_tc<<<dim3(8, 32), 256, ST2_BYTES>>>(x, out, c);
        reduce_update_kernel<<<1, 256>>>(out, c);
    }
}

// round 16
// speedup vs baseline: 1.3826x; 1.3826x over previous
#include <cuda_runtime.h>
#include <cuda_fp16.h>
#include <cstdint>

typedef uint32_t u32;

#define CHUNKSZ 512
#define NCHUNK  8
#define HH      1024
#define FF      4096
#define MROWS   2048          /* rows per chunk (B*CHUNKSZ) */
#define MALL    16384         /* all rows (B*S) */
#define NOUT    16777216

// ---- scratch (device globals; no allocations allowed) ----
__device__ __half g_xh [(size_t)NOUT];         // fp16 x (32MB)
__device__ __half g_u0h[(size_t)MALL * FF];    // u0 all chunks (128MB)
__device__ __half g_u2h[(size_t)MALL * FF];    // u2 all chunks (128MB)
__device__ __half g_vh [(size_t)MROWS * FF];   // v, chunk-local (16MB)
__device__ __half g_w0T[(size_t)FF * HH];      // w0^T [n=4096][k=1024]
__device__ __half g_w2T[(size_t)FF * HH];
__device__ __half g_w1T[(size_t)HH * FF];      // w1^T [n=1024][k=4096]
__device__ float g_partial[256];
__device__ float g_D;
__device__ float g_total;

// =================== helpers ===================
__device__ __forceinline__ u32 smem_u32(const void* p) {
    u32 a; asm("{ .reg .u64 t; cvta.to.shared.u64 t, %1; cvt.u32.u64 %0, t; }" : "=r"(a) : "l"(p));
    return a;
}

#define CP16(dst, src) \
    asm volatile("cp.async.cg.shared.global [%0], [%1], 16;" :: "r"(dst), "l"(src) : "memory")
#define CPCOMMIT() asm volatile("cp.async.commit_group;" ::: "memory")
#define CPWAIT1()  asm volatile("cp.async.wait_group 1;" ::: "memory")
#define CPWAIT2()  asm volatile("cp.async.wait_group 2;" ::: "memory")

#define LDSM4(r, addr) \
    asm volatile("ldmatrix.sync.aligned.m8n8.x4.shared.b16 {%0,%1,%2,%3}, [%4];" \
        : "=r"((r)[0]), "=r"((r)[1]), "=r"((r)[2]), "=r"((r)[3]) : "r"(addr))

#define MMA16(d, a, b0_, b1_) \
    asm volatile("mma.sync.aligned.m16n8k16.row.col.f32.f16.f16.f32 " \
        "{%0,%1,%2,%3}, {%4,%5,%6,%7}, {%8,%9}, {%0,%1,%2,%3};" \
        : "+f"((d)[0]), "+f"((d)[1]), "+f"((d)[2]), "+f"((d)[3]) \
        : "r"((a)[0]), "r"((a)[1]), "r"((a)[2]), "r"((a)[3]), "r"(b0_), "r"(b1_))

// rows x 64 k-halves (128B data), row stride 144B -> conflict-free LDSM/STS
#define ROWSTRB  144
#define TILE128  18432   /* 128*144 */
#define TILE64   9216    /*  64*144 */
#define MROWB    2304    /*  16*144 */

// =================== small kernels ===================
// part=0: convert chunk-0 rows only (rows c*512..c*512+511 of each batch segment).
// part=1: convert everything else.
__global__ void conv_x_kernel(const float* __restrict__ x, int part) {
    int tid = blockIdx.x * 256 + threadIdx.x;
    int i;
    if (part == 0) {
        // 4 segments x 512 rows x 1024 cols / 4 floats = 524288 threads? grid covers 2048 rows
        int rl = tid >> 8;                 // local row 0..2047
        int col4 = (tid & 255) * 4;        // 256 threads cover 1024 cols
        int grow = ((rl >> 9) << 12) + (rl & 511);   // chunk 0 rows
        i = grow * HH + col4;
    } else {
        // remaining rows: local row 0..14335 maps to rows with chunk index 1..7
        int rl = tid >> 8;
        int col4 = (tid & 255) * 4;
        int seg = rl / 3584, rem = rl % 3584;        // 4 segs x 7 chunks x 512 rows
        int grow = (seg << 12) + CHUNKSZ + rem;      // skip chunk-0 rows
        i = grow * HH + col4;
    }
    float4 v = *(const float4*)(x + i);
    *(__half2*)(g_xh + i)     = __floats2half2_rn(v.x, v.y);
    *(__half2*)(g_xh + i + 2) = __floats2half2_rn(v.z, v.w);
    if (part == 0 && blockIdx.x == 0 && threadIdx.x == 0) { g_D = 1.0f; g_total = 0.0f; }
}

// 3 transposes in one launch (z selects weight); out[C][R] = half(in[R][C])
__global__ void transpose_all(const float* __restrict__ w0, const float* __restrict__ w1,
                              const float* __restrict__ w2) {
    __shared__ float t[32][33];
    int z = blockIdx.z;
    const float* in; __half* out; int R, C, c0, r0;
    if (z == 0)      { in = w0; out = g_w0T; R = HH; C = FF; c0 = blockIdx.x * 32; r0 = blockIdx.y * 32; }
    else if (z == 1) { in = w2; out = g_w2T; R = HH; C = FF; c0 = blockIdx.x * 32; r0 = blockIdx.y * 32; }
    else             { in = w1; out = g_w1T; R = FF; C = HH; c0 = blockIdx.y * 32; r0 = blockIdx.x * 32; }
    #pragma unroll
    for (int i = 0; i < 32; i += 8)
        t[threadIdx.y + i][threadIdx.x] = in[(size_t)(r0 + threadIdx.y + i) * C + c0 + threadIdx.x];
    __syncthreads();
    #pragma unroll
    for (int i = 0; i < 32; i += 8)
        out[(size_t)(c0 + threadIdx.y + i) * R + r0 + threadIdx.x] = __float2half_rn(t[threadIdx.x][threadIdx.y + i]);
}

// vh[row_local] = silu(D*u0[grow]) * u2[grow], 8 halves/thread
__global__ void silu_mul_kernel(int chunk) {
    const float D = g_D;
    size_t idx = ((size_t)blockIdx.x * 256 + threadIdx.x) * 8;
    int rl  = (int)(idx >> 12);
    int col = (int)(idx & 4095);
    int grow = ((rl >> 9) << 12) + chunk * CHUNKSZ + (rl & 511);
    size_t gi = (size_t)grow * FF + col;
    uint4 a4 = *(const uint4*)(g_u0h + gi);
    uint4 b4 = *(const uint4*)(g_u2h + gi);
    const __half2* a = (const __half2*)&a4;
    const __half2* b = (const __half2*)&b4;
    uint4 o4;
    __half2* o = (__half2*)&o4;
    #pragma unroll
    for (int j = 0; j < 4; j++) {
        float2 af = __half22float2(a[j]);
        float2 bf = __half22float2(b[j]);
        float z0 = D * af.x, z1 = D * af.y;
        float s0 = z0 / (1.0f + __expf(-z0)), s1 = z1 / (1.0f + __expf(-z1));
        o[j] = __floats2half2_rn(s0 * bf.x, s1 * bf.y);
    }
    *(uint4*)(g_vh + (size_t)rl * FF + col) = o4;
}

__global__ void reduce_update_kernel(float* __restrict__ outp, int chunk) {
    __shared__ float red[256];
    int t = threadIdx.x;
    red[t] = g_partial[t];
    __syncthreads();
    for (int s = 128; s > 0; s >>= 1) {
        if (t < s) red[t] += red[t + s];
        __syncthreads();
    }
    if (t == 0) {
        float loss = red[0] * (1.0f / (float)(MROWS * HH));
        float tot = g_total + loss;
        g_total = tot;
        g_D = g_D * (1.0f - 0.001f * loss);
        if (chunk == NCHUNK - 1) outp[NOUT] = tot * (1.0f / (float)NCHUNK);
    }
}

// =================== GEMM1 (per chunk): u{0,2}[chunk rows] = x @ w{0,2}T ===================
// CTA 128x128, 256 thr (8 warps 4m x 2n, warp 32x64), K=1024, k-tile 64, 3 stages, occ 2.
#define ST1_STAGE (2 * TILE128)    /* 36864 */
#define ST1_BYTES (3 * ST1_STAGE)  /* 110592 */

__device__ __forceinline__ void g1_load(u32 base, const __half* wT, int tid,
                                        int m0, int n0, int kt) {
    #pragma unroll
    for (int i = 0; i < 4; i++) {
        int idx = tid + i * 256;
        int row = idx >> 3, kq = idx & 7;
        CP16(base + (u32)(row * ROWSTRB + kq * 16),
             g_xh + (size_t)(m0 + row) * HH + kt * 64 + kq * 8);
    }
    #pragma unroll
    for (int i = 0; i < 4; i++) {
        int idx = tid + i * 256;
        int row = idx >> 3, kq = idx & 7;
        CP16(base + TILE128 + (u32)(row * ROWSTRB + kq * 16),
             wT + (size_t)(n0 + row) * HH + kt * 64 + kq * 8);
    }
}

__global__ __launch_bounds__(256, 2)
void gemm1_tc(int chunk)
{
    extern __shared__ float smem[];
    const u32 sb = smem_u32(smem);
    const int tid = threadIdx.x, lane = tid & 31, wid = tid >> 5;
    const int wm = wid & 3, wn = wid >> 2;            // 4m x 2n warps, tile 32x64
    const int m0 = ((blockIdx.y >> 2) << 12) + chunk * CHUNKSZ + (blockIdx.y & 3) * 128;
    const int n0 = blockIdx.x * 128;
    const int z = blockIdx.z;
    const __half* wT = z ? g_w2T : g_w0T;
    __half* uout = z ? g_u2h : g_u0h;

    float acc[2][8][4];
    #pragma unroll
    for (int a = 0; a < 2; a++)
        #pragma unroll
        for (int b = 0; b < 8; b++)
            #pragma unroll
            for (int c = 0; c < 4; c++) acc[a][b][c] = 0.f;

    const u32 aoff = (u32)((wm * 32 + (lane & 15)) * ROWSTRB) + ((lane >> 4) & 1) * 16;
    const u32 boff = (u32)((wn * 64 + (lane & 15)) * ROWSTRB) + ((lane >> 4) & 1) * 16;

    g1_load(sb, wT, tid, m0, n0, 0); CPCOMMIT();
    g1_load(sb + ST1_STAGE, wT, tid, m0, n0, 1); CPCOMMIT();

    const int KT = HH / 64;  // 16
    for (int kt = 0; kt < KT; ++kt) {
        const u32 base = sb + (u32)(kt % 3) * ST1_STAGE;
        CPWAIT1();
        __syncthreads();
        if (kt + 2 < KT) g1_load(sb + (u32)((kt + 2) % 3) * ST1_STAGE, wT, tid, m0, n0, kt + 2);
        CPCOMMIT();
        #pragma unroll
        for (int ks = 0; ks < 4; ++ks) {
            u32 A[2][4];
            LDSM4(A[0], base + aoff + 0 * MROWB + ks * 32);
            LDSM4(A[1], base + aoff + 1 * MROWB + ks * 32);
            #pragma unroll
            for (int tp = 0; tp < 4; ++tp) {
                u32 b[4];
                LDSM4(b, base + TILE128 + boff + tp * MROWB + ks * 32);
                #pragma unroll
                for (int mt = 0; mt < 2; ++mt) {
                    MMA16(acc[mt][2 * tp],     A[mt], b[0], b[2]);
                    MMA16(acc[mt][2 * tp + 1], A[mt], b[1], b[3]);
                }
            }
        }
    }

    const int gq = lane >> 2, tg = lane & 3;
    #pragma unroll
    for (int mt = 0; mt < 2; ++mt) {
        #pragma unroll
        for (int nt = 0; nt < 8; ++nt) {
            const int col = n0 + wn * 64 + nt * 8 + tg * 2;
            #pragma unroll
            for (int h = 0; h < 2; ++h) {
                const int row = m0 + wm * 32 + mt * 16 + gq + h * 8;
                *(__half2*)&uout[(size_t)row * FF + col] =
                    __floats2half2_rn(acc[mt][nt][h * 2], acc[mt][nt][h * 2 + 1]);
            }
        }
    }
}

// =================== GEMM2: out = D^2 * (v @ w1T) + fused loss partials ===================
// CTA 64x128, 256 thr (8 warps 2m x 4n, warp 32x32), K=4096, k-tile 64, 4 stages, occ 2.
#define ST2_STAGE (TILE64 + TILE128)  /* 27648 */
#define ST2_BYTES (4 * ST2_STAGE)     /* 110592 */

__device__ __forceinline__ void g2_load(u32 base, int tid, int m0, int n0, int kt) {
    #pragma unroll
    for (int i = 0; i < 2; i++) {
        int idx = tid + i * 256;
        int row = idx >> 3, kq = idx & 7;
        CP16(base + (u32)(row * ROWSTRB + kq * 16),
             g_vh + (size_t)(m0 + row) * FF + kt * 64 + kq * 8);
    }
    #pragma unroll
    for (int i = 0; i < 4; i++) {
        int idx = tid + i * 256;
        int row = idx >> 3, kq = idx & 7;
        CP16(base + TILE64 + (u32)(row * ROWSTRB + kq * 16),
             g_w1T + (size_t)(n0 + row) * FF + kt * 64 + kq * 8);
    }
}

__global__ __launch_bounds__(256, 2)
void gemm2_tc(const float* __restrict__ x, float* __restrict__ outp, int chunk)
{
    extern __shared__ float smem[];
    const u32 sb = smem_u32(smem);
    const int tid = threadIdx.x, lane = tid & 31, wid = tid >> 5;
    const int wm = wid & 1, wn = wid >> 1;            // 2m x 4n warps, tile 32x32
    const int m0 = blockIdx.y * 64, n0 = blockIdx.x * 128;

    float acc[2][4][4];
    #pragma unroll
    for (int a = 0; a < 2; a++)
        #pragma unroll
        for (int b = 0; b < 4; b++)
            #pragma unroll
            for (int c = 0; c < 4; c++) acc[a][b][c] = 0.f;

    const u32 aoff = (u32)((wm * 32 + (lane & 15)) * ROWSTRB) + ((lane >> 4) & 1) * 16;
    const u32 boff = (u32)((wn * 32 + (lane & 15)) * ROWSTRB) + ((lane >> 4) & 1) * 16;

    g2_load(sb, tid, m0, n0, 0); CPCOMMIT();
    g2_load(sb + ST2_STAGE, tid, m0, n0, 1); CPCOMMIT();
    g2_load(sb + 2 * ST2_STAGE, tid, m0, n0, 2); CPCOMMIT();

    const int KT = FF / 64;  // 64
    for (int kt = 0; kt < KT; ++kt) {
        const u32 base = sb + (u32)(kt & 3) * ST2_STAGE;
        CPWAIT2();
        __syncthreads();
        if (kt + 3 < KT) g2_load(sb + (u32)((kt + 3) & 3) * ST2_STAGE, tid, m0, n0, kt + 3);
        CPCOMMIT();
        #pragma unroll
        for (int ks = 0; ks < 4; ++ks) {
            u32 A[2][4], b0[4], b1[4];
            LDSM4(A[0], base + aoff + 0 * MROWB + ks * 32);
            LDSM4(A[1], base + aoff + 1 * MROWB + ks * 32);
            LDSM4(b0, base + TILE64 + boff + 0 * MROWB + ks * 32);
            LDSM4(b1, base + TILE64 + boff + 1 * MROWB + ks * 32);
            #pragma unroll
            for (int mt = 0; mt < 2; ++mt) {
                MMA16(acc[mt][0], A[mt], b0[0], b0[2]);
                MMA16(acc[mt][1], A[mt], b0[1], b0[3]);
                MMA16(acc[mt][2], A[mt], b1[0], b1[2]);
                MMA16(acc[mt][3], A[mt], b1[1], b1[3]);
            }
        }
    }

    const float D = g_D, D2 = D * D;
    const int gq = lane >> 2, tg = lane & 3;
    float sq = 0.0f;
    #pragma unroll
    for (int mt = 0; mt < 2; ++mt) {
        #pragma unroll
        for (int nt = 0; nt < 4; ++nt) {
            const int col = n0 + wn * 32 + nt * 8 + tg * 2;
            #pragma unroll
            for (int h = 0; h < 2; ++h) {
                const int lm = m0 + wm * 32 + mt * 16 + gq + h * 8;
                const int g = ((lm >> 9) << 12) + chunk * CHUNKSZ + (lm & 511);
                float2 xv = *(const float2*)(x + (size_t)g * HH + col);
                float2 ov;
                ov.x = D2 * acc[mt][nt][h * 2];
                ov.y = D2 * acc[mt][nt][h * 2 + 1];
                *(float2*)(outp + (size_t)g * HH + col) = ov;
                float d0 = ov.x - xv.x, d1 = ov.y - xv.y;
                sq += d0 * d0 + d1 * d1;
            }
        }
    }
    #pragma unroll
    for (int off = 16; off > 0; off >>= 1)
        sq += __shfl_xor_sync(0xFFFFFFFFu, sq, off);
    __syncthreads();
    float* red = smem;
    if (lane == 0) red[wid] = sq;
    __syncthreads();
    if (tid == 0) {
        float s = 0.f;
        #pragma unroll
        for (int i = 0; i < 8; i++) s += red[i];
        g_partial[blockIdx.y * 8 + blockIdx.x] = s;
    }
}

// =================== host ===================
extern "C" void kernel_launch(void* const* d_in, const int* in_sizes, int n_in,
                              void* d_out, int out_size)
{
    const float* x  = (const float*)d_in[0];
    const float* w0 = (const float*)d_in[1];
    const float* w1 = (const float*)d_in[2];
    const float* w2 = (const float*)d_in[3];
    float* out = (float*)d_out;

    static cudaStream_t sS = nullptr;
    static cudaEvent_t evA = nullptr, evT = nullptr, evF = nullptr, e1[NCHUNK];
    if (!sS) {
        cudaStreamCreateWithFlags(&sS, cudaStreamNonBlocking);
        cudaEventCreateWithFlags(&evA, cudaEventDisableTiming);
        cudaEventCreateWithFlags(&evT, cudaEventDisableTiming);
        cudaEventCreateWithFlags(&evF, cudaEventDisableTiming);
        for (int c = 0; c < NCHUNK; ++c)
            cudaEventCreateWithFlags(&e1[c], cudaEventDisableTiming);
        cudaFuncSetAttribute(gemm1_tc, cudaFuncAttributeMaxDynamicSharedMemorySize, ST1_BYTES);
        cudaFuncSetAttribute(gemm2_tc, cudaFuncAttributeMaxDynamicSharedMemorySize, ST2_BYTES);
    }

    // prologue: main stream converts chunk-0 x; side stream does transposes + rest of x
    cudaEventRecord(evA, 0);
    cudaStreamWaitEvent(sS, evA, 0);
    transpose_all<<<dim3(128, 32, 3), dim3(32, 8), 0, sS>>>(w0, w1, w2);
    conv_x_kernel<<<(MROWS * HH / 4) / 256, 256>>>(x, 0);            // chunk-0 rows (main)
    conv_x_kernel<<<((MALL - MROWS) * HH / 4) / 256, 256, 0, sS>>>(x, 1);  // rest (side)
    cudaEventRecord(evT, sS);
    cudaStreamWaitEvent(0, evT, 0);        // gemm1(0) needs w0T/w2T (transpose on side)

    // chunk 0's gemm1 on the main stream (needs only chunk-0 xh + wT)
    gemm1_tc<<<dim3(32, 16, 2), 256, ST1_BYTES>>>(0);

    // fork: side stream computes gemm1 for chunks 1..7 concurrently with the chain
    cudaEventRecord(evF, 0);
    cudaStreamWaitEvent(sS, evF, 0);
    for (int c = 1; c < NCHUNK; ++c) {
        gemm1_tc<<<dim3(32, 16, 2), 256, ST1_BYTES, sS>>>(c);
        cudaEventRecord(e1[c], sS);
    }

    // serial D-recurrence chain on the main stream; chain(c) gated on gemm1(c)
    for (int c = 0; c < NCHUNK; ++c) {
        if (c > 0) cudaStreamWaitEvent(0, e1[c], 0);   // joins side stream by c=7
        silu_mul_kernel<<<(MROWS * FF) / 2048, 256>>>(c);
        gemm2_tc<<<dim3(8, 32), 256, ST2_BYTES>>>(x, out, c);
        reduce_update_kernel<<<1, 256>>>(out, c);
    }
}